// round 9
// baseline (speedup 1.0000x reference)
#include <cuda_runtime.h>
#include <cuda_fp16.h>
#include <cstdint>

#define BQ     2
#define NSEQ   4096
#define DMODEL 512
#define NH     8
#define HDIM   64
#define WSTR   72   // proj smem stride (halves): 144B rows, ldmatrix conflict-free
#define KSTR   72   // attn K-tile stride (halves)

// Scratch (allocation-free __device__ globals), fp16, 8 MB each.
__device__ __half g_q[BQ*NH*NSEQ*HDIM];   // [b,h,n,hd], pre-scaled by D^-0.5*log2e
__device__ __half g_k[BQ*NH*NSEQ*HDIM];   // [b,h,n,hd]  (v == k per reference bug)

// ---------------------------------------------------------------------------
// helpers (base sm_103 PTX only)
// ---------------------------------------------------------------------------
__device__ __forceinline__ uint32_t smem_u32(const void* p) {
    uint32_t a;
    asm("{ .reg .u64 t; cvta.to.shared.u64 t, %1; cvt.u32.u64 %0, t; }" : "=r"(a) : "l"(p));
    return a;
}
// pack two f32 into f16x2 (first arg -> high half)
__device__ __forceinline__ uint32_t cvt_h2(float hi, float lo) {
    uint32_t r; asm("cvt.rn.f16x2.f32 %0, %1, %2;" : "=r"(r) : "f"(hi), "f"(lo)); return r;
}
// packed f16x2 exp2
__device__ __forceinline__ uint32_t h2ex2(uint32_t x) {
    uint32_t r; asm("ex2.approx.f16x2 %0, %1;" : "=r"(r) : "r"(x)); return r;
}
// fp16: D += A(16x16) * B(16x8), fp32 accum
__device__ __forceinline__ void mma16(float* c, const uint32_t* a, uint32_t b0, uint32_t b1) {
    asm volatile("mma.sync.aligned.m16n8k16.row.col.f32.f16.f16.f32 "
        "{%0,%1,%2,%3}, {%4,%5,%6,%7}, {%8,%9}, {%0,%1,%2,%3};"
        : "+f"(c[0]), "+f"(c[1]), "+f"(c[2]), "+f"(c[3])
        : "r"(a[0]), "r"(a[1]), "r"(a[2]), "r"(a[3]), "r"(b0), "r"(b1));
}
__device__ __forceinline__ void ldsm4(uint32_t* r, uint32_t addr) {
    asm volatile("ldmatrix.sync.aligned.m8n8.x4.shared.b16 {%0,%1,%2,%3}, [%4];"
        : "=r"(r[0]), "=r"(r[1]), "=r"(r[2]), "=r"(r[3]) : "r"(addr));
}
__device__ __forceinline__ void ldsm4t(uint32_t* r, uint32_t addr) {
    asm volatile("ldmatrix.sync.aligned.m8n8.x4.trans.shared.b16 {%0,%1,%2,%3}, [%4];"
        : "=r"(r[0]), "=r"(r[1]), "=r"(r[2]), "=r"(r[3]) : "r"(addr));
}
__device__ __forceinline__ void cpa16(uint32_t dst, const void* src) {
    asm volatile("cp.async.cg.shared.global [%0], [%1], 16;" :: "r"(dst), "l"(src) : "memory");
}
#define CP_COMMIT() asm volatile("cp.async.commit_group;" ::: "memory")
#define CP_WAIT0()  asm volatile("cp.async.wait_group 0;" ::: "memory")
#define CP_WAIT1()  asm volatile("cp.async.wait_group 1;" ::: "memory")

__device__ __forceinline__ uint32_t pack_h2(float lo, float hi) {
    __half2 h = __floats2half2_rn(lo, hi);
    return *(uint32_t*)&h;
}

// ---------------------------------------------------------------------------
// Projection, fp16 mma m16n8k16 + ldmatrix + register-prefetch pipeline.
// ONE launch covers Q and K: blockIdx.z selects {W, bias, dst, oscale}.
// CTA: 256 thr / 8 warps; M=128 rows, N=64 (one head), K loop 8 x 64.
// smem: Xh[128][WSTR] + Wh[64][WSTR] halves = 27648 B.
// ---------------------------------------------------------------------------
__global__ __launch_bounds__(256, 2) void proj_mma(const float* __restrict__ X,
                                                   const float* __restrict__ Wq,
                                                   const float* __restrict__ bqp,
                                                   const float* __restrict__ Wk,
                                                   const float* __restrict__ bkp,
                                                   float qscale)
{
    extern __shared__ __half smh[];
    __half* Xh = smh;                 // [128][WSTR]
    __half* Wh = smh + 128 * WSTR;    // [64][WSTR]
    const uint32_t xA = smem_u32(Xh);
    const uint32_t wA = smem_u32(Wh);

    const int tid  = threadIdx.x;
    const int w    = tid >> 5;
    const int lane = tid & 31;
    const int g    = lane >> 2;
    const int tg   = lane & 3;
    const int h  = blockIdx.x;
    const int m0 = blockIdx.y * 128;
    const int z  = blockIdx.z;        // 0 = Q, 1 = K
    const int e0 = h * 64;

    const float* W    = z ? Wk  : Wq;
    const float* bias = z ? bkp : bqp;
    __half* dst       = z ? g_k : g_q;
    const float oscale = z ? 1.0f : qscale;

    const int lrow = (lane & 7) + ((lane >> 3) & 1) * 8;
    const int lcol = ((lane >> 4) & 1) * 8;

    float4 xr[8], wr[4];
    auto ldg_tile = [&](int kc) {
        const int k0 = kc * 64;
        #pragma unroll
        for (int p = 0; p < 8; p++) {
            int f = tid + p * 256;
            int row = f >> 4, c4 = (f & 15) * 4;
            xr[p] = *(const float4*)&X[(size_t)(m0 + row) * DMODEL + k0 + c4];
        }
        #pragma unroll
        for (int p = 0; p < 4; p++) {
            int f = tid + p * 256;
            int row = f >> 4, c4 = (f & 15) * 4;
            wr[p] = *(const float4*)&W[(size_t)(e0 + row) * DMODEL + k0 + c4];
        }
    };
    auto sts_tile = [&]() {
        #pragma unroll
        for (int p = 0; p < 8; p++) {
            int f = tid + p * 256;
            int row = f >> 4, c4 = (f & 15) * 4;
            *(uint2*)&Xh[row * WSTR + c4] =
                make_uint2(pack_h2(xr[p].x, xr[p].y), pack_h2(xr[p].z, xr[p].w));
        }
        #pragma unroll
        for (int p = 0; p < 4; p++) {
            int f = tid + p * 256;
            int row = f >> 4, c4 = (f & 15) * 4;
            *(uint2*)&Wh[row * WSTR + c4] =
                make_uint2(pack_h2(wr[p].x, wr[p].y), pack_h2(wr[p].z, wr[p].w));
        }
    };

    ldg_tile(0);
    float acc[8][4] = {};

    for (int kc = 0; kc < DMODEL / 64; kc++) {
        __syncthreads();
        sts_tile();
        __syncthreads();
        if (kc + 1 < DMODEL / 64) ldg_tile(kc + 1);

        #pragma unroll
        for (int kb = 0; kb < 4; kb++) {
            uint32_t a[4];
            ldsm4(a, xA + (uint32_t)((w * 16 + lrow) * WSTR + kb * 16 + lcol) * 2);
            #pragma unroll
            for (int wb = 0; wb < 4; wb++) {
                uint32_t r[4];
                ldsm4(r, wA + (uint32_t)((wb * 16 + lrow) * WSTR + kb * 16 + lcol) * 2);
                mma16(acc[2 * wb],     a, r[0], r[2]);
                mma16(acc[2 * wb + 1], a, r[1], r[3]);
            }
        }
    }

    const int b_ = m0 / NSEQ;
    const int n0 = m0 % NSEQ;
    const size_t obase = ((size_t)(b_ * NH + h) * NSEQ + n0 + w * 16 + g) * HDIM;
    #pragma unroll
    for (int nb = 0; nb < 8; nb++) {
        const int e = nb * 8 + 2 * tg;
        const float bv0 = bias[e0 + e], bv1 = bias[e0 + e + 1];
        uint32_t u0 = pack_h2((acc[nb][0] + bv0) * oscale, (acc[nb][1] + bv1) * oscale);
        uint32_t u1 = pack_h2((acc[nb][2] + bv0) * oscale, (acc[nb][3] + bv1) * oscale);
        *(uint32_t*)&dst[obase + e]            = u0;
        *(uint32_t*)&dst[obase + 8 * HDIM + e] = u1;
    }
}

// ---------------------------------------------------------------------------
// Flash attention, fp16 mma.sync m16n8k16. KV tile = 64 (proven best).
// Softmax: s -> f16x2 -> ex2.approx.f16x2 gives the PV A-frag directly.
// Row sums via an extra mma against an all-ones B-frag (exact fp32 sums of
// the SAME rounded P the PV uses; no FADD chain, no epilogue shuffles).
// smem: 2 x [64][KSTR] halves = 18432 B; 2 CTAs/SM.
// ---------------------------------------------------------------------------
__global__ __launch_bounds__(256, 2) void attn_mma(float* __restrict__ out)
{
    extern __shared__ __half smh[];
    const uint32_t ks0 = smem_u32(smh);
    const uint32_t ks1 = ks0 + 64 * KSTR * 2;
    const uint32_t ONES = 0x3C003C00u;   // f16x2 {1.0, 1.0}

    const int tid  = threadIdx.x;
    const int w    = tid >> 5;
    const int lane = tid & 31;
    const int g    = lane >> 2;
    const int tg   = lane & 3;
    const int bh = blockIdx.y;
    const int q0 = blockIdx.x * 128;

    const __half* kbase = g_k + (size_t)bh * NSEQ * HDIM;

    const int lrow = (lane & 7) + ((lane >> 3) & 1) * 8;
    const int lcol = ((lane >> 4) & 1) * 8;
    const uint32_t lbase = (uint32_t)(lrow * KSTR + lcol) * 2;

    uint32_t qf[4][4];
    {
        const __half* qr = g_q + ((size_t)bh * NSEQ + q0 + w * 16 + g) * HDIM;
        #pragma unroll
        for (int kb = 0; kb < 4; kb++) {
            const int c = kb * 16 + 2 * tg;
            qf[kb][0] = *(const uint32_t*)&qr[c];
            qf[kb][1] = *(const uint32_t*)&qr[c + 8 * HDIM];
            qf[kb][2] = *(const uint32_t*)&qr[c + 8];
            qf[kb][3] = *(const uint32_t*)&qr[c + 8 * HDIM + 8];
        }
    }

    {
        #pragma unroll
        for (int p = 0; p < 2; p++) {
            int f = tid + p * 256;
            int row = f >> 3, c = f & 7;
            cpa16(ks0 + (uint32_t)(row * KSTR + c * 8) * 2, kbase + row * HDIM + c * 8);
        }
        CP_COMMIT();
    }

    float o[8][4] = {};
    float li[4] = {};

    for (int t = 0; t < NSEQ / 64; t++) {
        __syncthreads();
        if (t + 1 < NSEQ / 64) {
            const __half* kt = kbase + (size_t)(t + 1) * 64 * HDIM;
            const uint32_t dstb = ((t + 1) & 1) ? ks1 : ks0;
            #pragma unroll
            for (int p = 0; p < 2; p++) {
                int f = tid + p * 256;
                int row = f >> 3, c = f & 7;
                cpa16(dstb + (uint32_t)(row * KSTR + c * 8) * 2, kt + row * HDIM + c * 8);
            }
            CP_COMMIT();
            CP_WAIT1();
        } else {
            CP_WAIT0();
        }
        __syncthreads();

        const uint32_t K = (t & 1) ? ks1 : ks0;

        #pragma unroll
        for (int j = 0; j < 4; j++) {
            float s0[4] = {}, s1[4] = {};
            #pragma unroll
            for (int kb = 0; kb < 4; kb++) {
                uint32_t r[4];
                ldsm4(r, K + lbase + (uint32_t)(j * 16 * KSTR + kb * 16) * 2);
                mma16(s0, qf[kb], r[0], r[2]);
                mma16(s1, qf[kb], r[1], r[3]);
            }
            // P = exp2(S) fully packed: cvt f32x2->f16x2, then f16x2 exp2
            uint32_t a[4];
            a[0] = h2ex2(cvt_h2(s0[1], s0[0]));
            a[1] = h2ex2(cvt_h2(s0[3], s0[2]));
            a[2] = h2ex2(cvt_h2(s1[1], s1[0]));
            a[3] = h2ex2(cvt_h2(s1[3], s1[2]));
            // row sums of P via ones-mma (exact fp32 accumulation)
            mma16(li, a, ONES, ONES);
            #pragma unroll
            for (int p = 0; p < 4; p++) {
                uint32_t v[4];
                ldsm4t(v, K + lbase + (uint32_t)(j * 16 * KSTR + p * 16) * 2);
                mma16(o[2 * p],     a, v[0], v[1]);
                mma16(o[2 * p + 1], a, v[2], v[3]);
            }
        }
    }

    // li[0] = full row sum (row g), li[2] = row g+8 — identical across columns
    const float inv0 = 1.0f / li[0];
    const float inv1 = 1.0f / li[2];

    const int b_ = bh >> 3;
    const int h  = bh & 7;
    const int row0 = q0 + w * 16 + g;
    #pragma unroll
    for (int nb = 0; nb < 8; nb++) {
        const int col = h * HDIM + nb * 8 + 2 * tg;
        *(float2*)&out[((size_t)b_ * NSEQ + row0) * DMODEL + col] =
            make_float2(o[nb][0] * inv0, o[nb][1] * inv0);
        *(float2*)&out[((size_t)b_ * NSEQ + row0 + 8) * DMODEL + col] =
            make_float2(o[nb][2] * inv1, o[nb][3] * inv1);
    }
}

extern "C" void kernel_launch(void* const* d_in, const int* in_sizes, int n_in,
                              void* d_out, int out_size)
{
    const float* x  = (const float*)d_in[0];
    const float* Wq = (const float*)d_in[1];
    const float* bq = (const float*)d_in[2];
    const float* Wk = (const float*)d_in[3];
    const float* bk = (const float*)d_in[4];
    float* out = (float*)d_out;

    const int psmem = 192 * WSTR * 2;        // 27648 B
    const int asmem = 2 * 64 * KSTR * 2;     // 18432 B
    cudaFuncSetAttribute(proj_mma, cudaFuncAttributeMaxDynamicSharedMemorySize, psmem);
    cudaFuncSetAttribute(attn_mma, cudaFuncAttributeMaxDynamicSharedMemorySize, asmem);

    const float qscale = 0.044194173824159216f * 1.4426950408889634f; // D^-1/2 * log2e

    proj_mma<<<dim3(NH, (BQ * NSEQ) / 128, 2), 256, psmem>>>(x, Wq, bq, Wk, bk, qscale);
    attn_mma<<<dim3(NSEQ / 128, BQ * NH), 256, asmem>>>(out);
}

// round 10
// speedup vs baseline: 1.0533x; 1.0533x over previous
#include <cuda_runtime.h>
#include <cuda_fp16.h>
#include <cstdint>

#define BQ     2
#define NSEQ   4096
#define DMODEL 512
#define NH     8
#define HDIM   64
#define WSTR   72   // proj smem stride (halves)
#define KSTR   72   // attn K-tile stride (halves)

// Scratch (allocation-free __device__ globals), fp16, 8 MB each.
__device__ __half g_q[BQ*NH*NSEQ*HDIM];   // [b,h,n,hd], pre-scaled by D^-0.5*log2e
__device__ __half g_k[BQ*NH*NSEQ*HDIM];   // [b,h,n,hd]  (v == k per reference bug)

// ---------------------------------------------------------------------------
// helpers (base sm_103 PTX only)
// ---------------------------------------------------------------------------
__device__ __forceinline__ uint32_t smem_u32(const void* p) {
    uint32_t a;
    asm("{ .reg .u64 t; cvta.to.shared.u64 t, %1; cvt.u32.u64 %0, t; }" : "=r"(a) : "l"(p));
    return a;
}
__device__ __forceinline__ uint32_t cvt_h2(float hi, float lo) {
    uint32_t r; asm("cvt.rn.f16x2.f32 %0, %1, %2;" : "=r"(r) : "f"(hi), "f"(lo)); return r;
}
__device__ __forceinline__ uint32_t h2ex2(uint32_t x) {
    uint32_t r; asm("ex2.approx.f16x2 %0, %1;" : "=r"(r) : "r"(x)); return r;
}
// fp16: D += A(16x16) * B(16x8), fp32 accum
__device__ __forceinline__ void mma16(float* c, const uint32_t* a, uint32_t b0, uint32_t b1) {
    asm volatile("mma.sync.aligned.m16n8k16.row.col.f32.f16.f16.f32 "
        "{%0,%1,%2,%3}, {%4,%5,%6,%7}, {%8,%9}, {%0,%1,%2,%3};"
        : "+f"(c[0]), "+f"(c[1]), "+f"(c[2]), "+f"(c[3])
        : "r"(a[0]), "r"(a[1]), "r"(a[2]), "r"(a[3]), "r"(b0), "r"(b1));
}
__device__ __forceinline__ void ldsm4(uint32_t* r, uint32_t addr) {
    asm volatile("ldmatrix.sync.aligned.m8n8.x4.shared.b16 {%0,%1,%2,%3}, [%4];"
        : "=r"(r[0]), "=r"(r[1]), "=r"(r[2]), "=r"(r[3]) : "r"(addr));
}
__device__ __forceinline__ void ldsm4t(uint32_t* r, uint32_t addr) {
    asm volatile("ldmatrix.sync.aligned.m8n8.x4.trans.shared.b16 {%0,%1,%2,%3}, [%4];"
        : "=r"(r[0]), "=r"(r[1]), "=r"(r[2]), "=r"(r[3]) : "r"(addr));
}
__device__ __forceinline__ void cpa16(uint32_t dst, const void* src) {
    asm volatile("cp.async.cg.shared.global [%0], [%1], 16;" :: "r"(dst), "l"(src) : "memory");
}
#define CP_COMMIT() asm volatile("cp.async.commit_group;" ::: "memory")
#define CP_WAIT0()  asm volatile("cp.async.wait_group 0;" ::: "memory")
#define CP_WAIT1()  asm volatile("cp.async.wait_group 1;" ::: "memory")

__device__ __forceinline__ uint32_t pack_h2(float lo, float hi) {
    __half2 h = __floats2half2_rn(lo, hi);
    return *(uint32_t*)&h;
}

// ---------------------------------------------------------------------------
// Projection (unchanged from R8/R9 merged version): one launch, z selects Q/K.
// ---------------------------------------------------------------------------
__global__ __launch_bounds__(256, 2) void proj_mma(const float* __restrict__ X,
                                                   const float* __restrict__ Wq,
                                                   const float* __restrict__ bqp,
                                                   const float* __restrict__ Wk,
                                                   const float* __restrict__ bkp,
                                                   float qscale)
{
    extern __shared__ __half smh[];
    __half* Xh = smh;                 // [128][WSTR]
    __half* Wh = smh + 128 * WSTR;    // [64][WSTR]
    const uint32_t xA = smem_u32(Xh);
    const uint32_t wA = smem_u32(Wh);

    const int tid  = threadIdx.x;
    const int w    = tid >> 5;
    const int lane = tid & 31;
    const int g    = lane >> 2;
    const int tg   = lane & 3;
    const int h  = blockIdx.x;
    const int m0 = blockIdx.y * 128;
    const int z  = blockIdx.z;        // 0 = Q, 1 = K
    const int e0 = h * 64;

    const float* W    = z ? Wk  : Wq;
    const float* bias = z ? bkp : bqp;
    __half* dst       = z ? g_k : g_q;
    const float oscale = z ? 1.0f : qscale;

    const int lrow = (lane & 7) + ((lane >> 3) & 1) * 8;
    const int lcol = ((lane >> 4) & 1) * 8;

    float4 xr[8], wr[4];
    auto ldg_tile = [&](int kc) {
        const int k0 = kc * 64;
        #pragma unroll
        for (int p = 0; p < 8; p++) {
            int f = tid + p * 256;
            int row = f >> 4, c4 = (f & 15) * 4;
            xr[p] = *(const float4*)&X[(size_t)(m0 + row) * DMODEL + k0 + c4];
        }
        #pragma unroll
        for (int p = 0; p < 4; p++) {
            int f = tid + p * 256;
            int row = f >> 4, c4 = (f & 15) * 4;
            wr[p] = *(const float4*)&W[(size_t)(e0 + row) * DMODEL + k0 + c4];
        }
    };
    auto sts_tile = [&]() {
        #pragma unroll
        for (int p = 0; p < 8; p++) {
            int f = tid + p * 256;
            int row = f >> 4, c4 = (f & 15) * 4;
            *(uint2*)&Xh[row * WSTR + c4] =
                make_uint2(pack_h2(xr[p].x, xr[p].y), pack_h2(xr[p].z, xr[p].w));
        }
        #pragma unroll
        for (int p = 0; p < 4; p++) {
            int f = tid + p * 256;
            int row = f >> 4, c4 = (f & 15) * 4;
            *(uint2*)&Wh[row * WSTR + c4] =
                make_uint2(pack_h2(wr[p].x, wr[p].y), pack_h2(wr[p].z, wr[p].w));
        }
    };

    ldg_tile(0);
    float acc[8][4] = {};

    for (int kc = 0; kc < DMODEL / 64; kc++) {
        __syncthreads();
        sts_tile();
        __syncthreads();
        if (kc + 1 < DMODEL / 64) ldg_tile(kc + 1);

        #pragma unroll
        for (int kb = 0; kb < 4; kb++) {
            uint32_t a[4];
            ldsm4(a, xA + (uint32_t)((w * 16 + lrow) * WSTR + kb * 16 + lcol) * 2);
            #pragma unroll
            for (int wb = 0; wb < 4; wb++) {
                uint32_t r[4];
                ldsm4(r, wA + (uint32_t)((wb * 16 + lrow) * WSTR + kb * 16 + lcol) * 2);
                mma16(acc[2 * wb],     a, r[0], r[2]);
                mma16(acc[2 * wb + 1], a, r[1], r[3]);
            }
        }
    }

    const int b_ = m0 / NSEQ;
    const int n0 = m0 % NSEQ;
    const size_t obase = ((size_t)(b_ * NH + h) * NSEQ + n0 + w * 16 + g) * HDIM;
    #pragma unroll
    for (int nb = 0; nb < 8; nb++) {
        const int e = nb * 8 + 2 * tg;
        const float bv0 = bias[e0 + e], bv1 = bias[e0 + e + 1];
        uint32_t u0 = pack_h2((acc[nb][0] + bv0) * oscale, (acc[nb][1] + bv1) * oscale);
        uint32_t u1 = pack_h2((acc[nb][2] + bv0) * oscale, (acc[nb][3] + bv1) * oscale);
        *(uint32_t*)&dst[obase + e]            = u0;
        *(uint32_t*)&dst[obase + 8 * HDIM + e] = u1;
    }
}

// ---------------------------------------------------------------------------
// Flash attention, fp16 mma. WARP-M = 32: each warp owns 32 q rows (two
// m16 A-sets) so every K/V fragment load feeds 2x the MMA work -> LDSM
// traffic per CTA halved (the R9 bottleneck). CTA = 128 thr / 4 warps =
// 128 q rows; 3 CTAs/SM. KV tile 64, cp.async double-buffered.
// Softmax: packed f16x2 exp2; row sums via ones-mma.
// smem: 2 x [64][KSTR] halves = 18432 B.
// ---------------------------------------------------------------------------
__global__ __launch_bounds__(128, 3) void attn_mma(float* __restrict__ out)
{
    extern __shared__ __half smh[];
    const uint32_t ks0 = smem_u32(smh);
    const uint32_t ks1 = ks0 + 64 * KSTR * 2;
    const uint32_t ONES = 0x3C003C00u;   // f16x2 {1.0, 1.0}

    const int tid  = threadIdx.x;
    const int w    = tid >> 5;            // 0..3
    const int lane = tid & 31;
    const int g    = lane >> 2;
    const int tg   = lane & 3;
    const int bh = blockIdx.y;
    const int q0 = blockIdx.x * 128;

    const __half* kbase = g_k + (size_t)bh * NSEQ * HDIM;

    const int lrow = (lane & 7) + ((lane >> 3) & 1) * 8;
    const int lcol = ((lane >> 4) & 1) * 8;
    const uint32_t lbase = (uint32_t)(lrow * KSTR + lcol) * 2;

    // Two Q A-frag sets: rows w*32 + [0,16) and + [16,32)
    uint32_t qfA[4][4], qfB[4][4];
    {
        const __half* qr = g_q + ((size_t)bh * NSEQ + q0 + w * 32 + g) * HDIM;
        #pragma unroll
        for (int kb = 0; kb < 4; kb++) {
            const int c = kb * 16 + 2 * tg;
            qfA[kb][0] = *(const uint32_t*)&qr[c];
            qfA[kb][1] = *(const uint32_t*)&qr[c + 8 * HDIM];
            qfA[kb][2] = *(const uint32_t*)&qr[c + 8];
            qfA[kb][3] = *(const uint32_t*)&qr[c + 8 * HDIM + 8];
            qfB[kb][0] = *(const uint32_t*)&qr[c + 16 * HDIM];
            qfB[kb][1] = *(const uint32_t*)&qr[c + 24 * HDIM];
            qfB[kb][2] = *(const uint32_t*)&qr[c + 16 * HDIM + 8];
            qfB[kb][3] = *(const uint32_t*)&qr[c + 24 * HDIM + 8];
        }
    }

    // prefetch tile 0: 64 rows x 8 chunks = 512 / 128 thr = 4 each
    {
        #pragma unroll
        for (int p = 0; p < 4; p++) {
            int f = tid + p * 128;
            int row = f >> 3, c = f & 7;
            cpa16(ks0 + (uint32_t)(row * KSTR + c * 8) * 2, kbase + row * HDIM + c * 8);
        }
        CP_COMMIT();
    }

    float o[16][4] = {};        // [0..7] = A-set hd blocks, [8..15] = B-set
    float liA[4] = {}, liB[4] = {};

    for (int t = 0; t < NSEQ / 64; t++) {
        __syncthreads();
        if (t + 1 < NSEQ / 64) {
            const __half* kt = kbase + (size_t)(t + 1) * 64 * HDIM;
            const uint32_t dstb = ((t + 1) & 1) ? ks1 : ks0;
            #pragma unroll
            for (int p = 0; p < 4; p++) {
                int f = tid + p * 128;
                int row = f >> 3, c = f & 7;
                cpa16(dstb + (uint32_t)(row * KSTR + c * 8) * 2, kt + row * HDIM + c * 8);
            }
            CP_COMMIT();
            CP_WAIT1();
        } else {
            CP_WAIT0();
        }
        __syncthreads();

        const uint32_t K = (t & 1) ? ks1 : ks0;

        #pragma unroll
        for (int j = 0; j < 4; j++) {
            // ---- S: 32q x 16kv, one frag load serves both A-sets ----
            float sA0[4] = {}, sA1[4] = {}, sB0[4] = {}, sB1[4] = {};
            #pragma unroll
            for (int kb = 0; kb < 4; kb++) {
                uint32_t r[4];
                ldsm4(r, K + lbase + (uint32_t)(j * 16 * KSTR + kb * 16) * 2);
                mma16(sA0, qfA[kb], r[0], r[2]);
                mma16(sA1, qfA[kb], r[1], r[3]);
                mma16(sB0, qfB[kb], r[0], r[2]);
                mma16(sB1, qfB[kb], r[1], r[3]);
            }
            // ---- P = exp2(S), packed ----
            uint32_t aA[4], aB[4];
            aA[0] = h2ex2(cvt_h2(sA0[1], sA0[0]));
            aA[1] = h2ex2(cvt_h2(sA0[3], sA0[2]));
            aA[2] = h2ex2(cvt_h2(sA1[1], sA1[0]));
            aA[3] = h2ex2(cvt_h2(sA1[3], sA1[2]));
            aB[0] = h2ex2(cvt_h2(sB0[1], sB0[0]));
            aB[1] = h2ex2(cvt_h2(sB0[3], sB0[2]));
            aB[2] = h2ex2(cvt_h2(sB1[1], sB1[0]));
            aB[3] = h2ex2(cvt_h2(sB1[3], sB1[2]));
            mma16(liA, aA, ONES, ONES);
            mma16(liB, aB, ONES, ONES);
            // ---- PV: one transposed frag load serves both A-sets ----
            #pragma unroll
            for (int p = 0; p < 4; p++) {
                uint32_t v[4];
                ldsm4t(v, K + lbase + (uint32_t)(j * 16 * KSTR + p * 16) * 2);
                mma16(o[2 * p],         aA, v[0], v[1]);
                mma16(o[2 * p + 1],     aA, v[2], v[3]);
                mma16(o[8 + 2 * p],     aB, v[0], v[1]);
                mma16(o[8 + 2 * p + 1], aB, v[2], v[3]);
            }
        }
    }

    const float invA0 = 1.0f / liA[0];
    const float invA1 = 1.0f / liA[2];
    const float invB0 = 1.0f / liB[0];
    const float invB1 = 1.0f / liB[2];

    const int b_ = bh >> 3;
    const int h  = bh & 7;
    const size_t rbase = (size_t)b_ * NSEQ + q0 + w * 32 + g;
    #pragma unroll
    for (int nb = 0; nb < 8; nb++) {
        const int col = h * HDIM + nb * 8 + 2 * tg;
        *(float2*)&out[(rbase)      * DMODEL + col] =
            make_float2(o[nb][0] * invA0, o[nb][1] * invA0);
        *(float2*)&out[(rbase + 8)  * DMODEL + col] =
            make_float2(o[nb][2] * invA1, o[nb][3] * invA1);
        *(float2*)&out[(rbase + 16) * DMODEL + col] =
            make_float2(o[8 + nb][0] * invB0, o[8 + nb][1] * invB0);
        *(float2*)&out[(rbase + 24) * DMODEL + col] =
            make_float2(o[8 + nb][2] * invB1, o[8 + nb][3] * invB1);
    }
}

extern "C" void kernel_launch(void* const* d_in, const int* in_sizes, int n_in,
                              void* d_out, int out_size)
{
    const float* x  = (const float*)d_in[0];
    const float* Wq = (const float*)d_in[1];
    const float* bq = (const float*)d_in[2];
    const float* Wk = (const float*)d_in[3];
    const float* bk = (const float*)d_in[4];
    float* out = (float*)d_out;

    const int psmem = 192 * WSTR * 2;        // 27648 B
    const int asmem = 2 * 64 * KSTR * 2;     // 18432 B
    cudaFuncSetAttribute(proj_mma, cudaFuncAttributeMaxDynamicSharedMemorySize, psmem);
    cudaFuncSetAttribute(attn_mma, cudaFuncAttributeMaxDynamicSharedMemorySize, asmem);

    const float qscale = 0.044194173824159216f * 1.4426950408889634f; // D^-1/2 * log2e

    proj_mma<<<dim3(NH, (BQ * NSEQ) / 128, 2), 256, psmem>>>(x, Wq, bq, Wk, bk, qscale);
    attn_mma<<<dim3(NSEQ / 128, BQ * NH), 128, asmem>>>(out);
}

// round 11
// speedup vs baseline: 1.0601x; 1.0064x over previous
#include <cuda_runtime.h>
#include <cuda_fp16.h>
#include <cstdint>

#define BQ     2
#define NSEQ   4096
#define DMODEL 512
#define NH     8
#define HDIM   64
#define WSTR   72   // proj smem stride (halves)
#define KSTR   72   // attn K-tile stride (halves)

// Scratch (allocation-free __device__ globals), fp16, 8 MB each.
__device__ __half g_q[BQ*NH*NSEQ*HDIM];   // [b,h,n,hd], pre-scaled by D^-0.5*log2e
__device__ __half g_k[BQ*NH*NSEQ*HDIM];   // [b,h,n,hd]  (v == k per reference bug)

// ---------------------------------------------------------------------------
// helpers (base sm_103 PTX only)
// ---------------------------------------------------------------------------
__device__ __forceinline__ uint32_t smem_u32(const void* p) {
    uint32_t a;
    asm("{ .reg .u64 t; cvta.to.shared.u64 t, %1; cvt.u32.u64 %0, t; }" : "=r"(a) : "l"(p));
    return a;
}
__device__ __forceinline__ uint32_t cvt_h2(float hi, float lo) {
    uint32_t r; asm("cvt.rn.f16x2.f32 %0, %1, %2;" : "=r"(r) : "f"(hi), "f"(lo)); return r;
}
__device__ __forceinline__ uint32_t h2ex2(uint32_t x) {
    uint32_t r; asm("ex2.approx.f16x2 %0, %1;" : "=r"(r) : "r"(x)); return r;
}
// fp16: D += A(16x16) * B(16x8), fp32 accum
__device__ __forceinline__ void mma16(float* c, const uint32_t* a, uint32_t b0, uint32_t b1) {
    asm volatile("mma.sync.aligned.m16n8k16.row.col.f32.f16.f16.f32 "
        "{%0,%1,%2,%3}, {%4,%5,%6,%7}, {%8,%9}, {%0,%1,%2,%3};"
        : "+f"(c[0]), "+f"(c[1]), "+f"(c[2]), "+f"(c[3])
        : "r"(a[0]), "r"(a[1]), "r"(a[2]), "r"(a[3]), "r"(b0), "r"(b1));
}
__device__ __forceinline__ void ldsm4(uint32_t* r, uint32_t addr) {
    asm volatile("ldmatrix.sync.aligned.m8n8.x4.shared.b16 {%0,%1,%2,%3}, [%4];"
        : "=r"(r[0]), "=r"(r[1]), "=r"(r[2]), "=r"(r[3]) : "r"(addr));
}
__device__ __forceinline__ void ldsm4t(uint32_t* r, uint32_t addr) {
    asm volatile("ldmatrix.sync.aligned.m8n8.x4.trans.shared.b16 {%0,%1,%2,%3}, [%4];"
        : "=r"(r[0]), "=r"(r[1]), "=r"(r[2]), "=r"(r[3]) : "r"(addr));
}
__device__ __forceinline__ void cpa16(uint32_t dst, const void* src) {
    asm volatile("cp.async.cg.shared.global [%0], [%1], 16;" :: "r"(dst), "l"(src) : "memory");
}
#define CP_COMMIT() asm volatile("cp.async.commit_group;" ::: "memory")
#define CP_WAIT0()  asm volatile("cp.async.wait_group 0;" ::: "memory")
#define CP_WAIT1()  asm volatile("cp.async.wait_group 1;" ::: "memory")

__device__ __forceinline__ uint32_t pack_h2(float lo, float hi) {
    __half2 h = __floats2half2_rn(lo, hi);
    return *(uint32_t*)&h;
}

// ---------------------------------------------------------------------------
// Projection (unchanged): one launch, blockIdx.z selects Q/K.
// ---------------------------------------------------------------------------
__global__ __launch_bounds__(256, 2) void proj_mma(const float* __restrict__ X,
                                                   const float* __restrict__ Wq,
                                                   const float* __restrict__ bqp,
                                                   const float* __restrict__ Wk,
                                                   const float* __restrict__ bkp,
                                                   float qscale)
{
    extern __shared__ __half smh[];
    __half* Xh = smh;                 // [128][WSTR]
    __half* Wh = smh + 128 * WSTR;    // [64][WSTR]
    const uint32_t xA = smem_u32(Xh);
    const uint32_t wA = smem_u32(Wh);

    const int tid  = threadIdx.x;
    const int w    = tid >> 5;
    const int lane = tid & 31;
    const int g    = lane >> 2;
    const int tg   = lane & 3;
    const int h  = blockIdx.x;
    const int m0 = blockIdx.y * 128;
    const int z  = blockIdx.z;        // 0 = Q, 1 = K
    const int e0 = h * 64;

    const float* W    = z ? Wk  : Wq;
    const float* bias = z ? bkp : bqp;
    __half* dst       = z ? g_k : g_q;
    const float oscale = z ? 1.0f : qscale;

    const int lrow = (lane & 7) + ((lane >> 3) & 1) * 8;
    const int lcol = ((lane >> 4) & 1) * 8;

    float4 xr[8], wr[4];
    auto ldg_tile = [&](int kc) {
        const int k0 = kc * 64;
        #pragma unroll
        for (int p = 0; p < 8; p++) {
            int f = tid + p * 256;
            int row = f >> 4, c4 = (f & 15) * 4;
            xr[p] = *(const float4*)&X[(size_t)(m0 + row) * DMODEL + k0 + c4];
        }
        #pragma unroll
        for (int p = 0; p < 4; p++) {
            int f = tid + p * 256;
            int row = f >> 4, c4 = (f & 15) * 4;
            wr[p] = *(const float4*)&W[(size_t)(e0 + row) * DMODEL + k0 + c4];
        }
    };
    auto sts_tile = [&]() {
        #pragma unroll
        for (int p = 0; p < 8; p++) {
            int f = tid + p * 256;
            int row = f >> 4, c4 = (f & 15) * 4;
            *(uint2*)&Xh[row * WSTR + c4] =
                make_uint2(pack_h2(xr[p].x, xr[p].y), pack_h2(xr[p].z, xr[p].w));
        }
        #pragma unroll
        for (int p = 0; p < 4; p++) {
            int f = tid + p * 256;
            int row = f >> 4, c4 = (f & 15) * 4;
            *(uint2*)&Wh[row * WSTR + c4] =
                make_uint2(pack_h2(wr[p].x, wr[p].y), pack_h2(wr[p].z, wr[p].w));
        }
    };

    ldg_tile(0);
    float acc[8][4] = {};

    for (int kc = 0; kc < DMODEL / 64; kc++) {
        __syncthreads();
        sts_tile();
        __syncthreads();
        if (kc + 1 < DMODEL / 64) ldg_tile(kc + 1);

        #pragma unroll
        for (int kb = 0; kb < 4; kb++) {
            uint32_t a[4];
            ldsm4(a, xA + (uint32_t)((w * 16 + lrow) * WSTR + kb * 16 + lcol) * 2);
            #pragma unroll
            for (int wb = 0; wb < 4; wb++) {
                uint32_t r[4];
                ldsm4(r, wA + (uint32_t)((wb * 16 + lrow) * WSTR + kb * 16 + lcol) * 2);
                mma16(acc[2 * wb],     a, r[0], r[2]);
                mma16(acc[2 * wb + 1], a, r[1], r[3]);
            }
        }
    }

    const int b_ = m0 / NSEQ;
    const int n0 = m0 % NSEQ;
    const size_t obase = ((size_t)(b_ * NH + h) * NSEQ + n0 + w * 16 + g) * HDIM;
    #pragma unroll
    for (int nb = 0; nb < 8; nb++) {
        const int e = nb * 8 + 2 * tg;
        const float bv0 = bias[e0 + e], bv1 = bias[e0 + e + 1];
        uint32_t u0 = pack_h2((acc[nb][0] + bv0) * oscale, (acc[nb][1] + bv1) * oscale);
        uint32_t u1 = pack_h2((acc[nb][2] + bv0) * oscale, (acc[nb][3] + bv1) * oscale);
        *(uint32_t*)&dst[obase + e]            = u0;
        *(uint32_t*)&dst[obase + 8 * HDIM + e] = u1;
    }
}

// ---------------------------------------------------------------------------
// Flash attention, fp16 mma, warp-M=32 (R10) + software-pipelined softmax:
// PV(j) is issued one stage behind S(j+1), so each warp's cvt/ex2 (MUFU)
// executes while ~34 queued MMAs drain on the tensor pipe.
// CTA = 128 thr / 4 warps = 128 q rows; 3 CTAs/SM; KV tile 64 double-buffered.
// ---------------------------------------------------------------------------
__global__ __launch_bounds__(128, 3) void attn_mma(float* __restrict__ out)
{
    extern __shared__ __half smh[];
    const uint32_t ks0 = smem_u32(smh);
    const uint32_t ks1 = ks0 + 64 * KSTR * 2;
    const uint32_t ONES = 0x3C003C00u;   // f16x2 {1.0, 1.0}

    const int tid  = threadIdx.x;
    const int w    = tid >> 5;            // 0..3
    const int lane = tid & 31;
    const int g    = lane >> 2;
    const int tg   = lane & 3;
    const int bh = blockIdx.y;
    const int q0 = blockIdx.x * 128;

    const __half* kbase = g_k + (size_t)bh * NSEQ * HDIM;

    const int lrow = (lane & 7) + ((lane >> 3) & 1) * 8;
    const int lcol = ((lane >> 4) & 1) * 8;
    const uint32_t lbase = (uint32_t)(lrow * KSTR + lcol) * 2;

    // Two Q A-frag sets: rows w*32 + [0,16) and + [16,32)
    uint32_t qfA[4][4], qfB[4][4];
    {
        const __half* qr = g_q + ((size_t)bh * NSEQ + q0 + w * 32 + g) * HDIM;
        #pragma unroll
        for (int kb = 0; kb < 4; kb++) {
            const int c = kb * 16 + 2 * tg;
            qfA[kb][0] = *(const uint32_t*)&qr[c];
            qfA[kb][1] = *(const uint32_t*)&qr[c + 8 * HDIM];
            qfA[kb][2] = *(const uint32_t*)&qr[c + 8];
            qfA[kb][3] = *(const uint32_t*)&qr[c + 8 * HDIM + 8];
            qfB[kb][0] = *(const uint32_t*)&qr[c + 16 * HDIM];
            qfB[kb][1] = *(const uint32_t*)&qr[c + 24 * HDIM];
            qfB[kb][2] = *(const uint32_t*)&qr[c + 16 * HDIM + 8];
            qfB[kb][3] = *(const uint32_t*)&qr[c + 24 * HDIM + 8];
        }
    }

    // prefetch tile 0
    {
        #pragma unroll
        for (int p = 0; p < 4; p++) {
            int f = tid + p * 128;
            int row = f >> 3, c = f & 7;
            cpa16(ks0 + (uint32_t)(row * KSTR + c * 8) * 2, kbase + row * HDIM + c * 8);
        }
        CP_COMMIT();
    }

    float o[16][4] = {};        // [0..7] = A-set hd blocks, [8..15] = B-set
    float liA[4] = {}, liB[4] = {};

    for (int t = 0; t < NSEQ / 64; t++) {
        __syncthreads();
        if (t + 1 < NSEQ / 64) {
            const __half* kt = kbase + (size_t)(t + 1) * 64 * HDIM;
            const uint32_t dstb = ((t + 1) & 1) ? ks1 : ks0;
            #pragma unroll
            for (int p = 0; p < 4; p++) {
                int f = tid + p * 128;
                int row = f >> 3, c = f & 7;
                cpa16(dstb + (uint32_t)(row * KSTR + c * 8) * 2, kt + row * HDIM + c * 8);
            }
            CP_COMMIT();
            CP_WAIT1();
        } else {
            CP_WAIT0();
        }
        __syncthreads();

        const uint32_t K = (t & 1) ? ks1 : ks0;

        float sA0[4], sA1[4], sB0[4], sB1[4];
        uint32_t aA[4], aB[4];

        auto do_S = [&](int j) {
            #pragma unroll
            for (int i = 0; i < 4; i++) { sA0[i] = 0.f; sA1[i] = 0.f; sB0[i] = 0.f; sB1[i] = 0.f; }
            #pragma unroll
            for (int kb = 0; kb < 4; kb++) {
                uint32_t r[4];
                ldsm4(r, K + lbase + (uint32_t)(j * 16 * KSTR + kb * 16) * 2);
                mma16(sA0, qfA[kb], r[0], r[2]);
                mma16(sA1, qfA[kb], r[1], r[3]);
                mma16(sB0, qfB[kb], r[0], r[2]);
                mma16(sB1, qfB[kb], r[1], r[3]);
            }
        };
        auto do_exp = [&]() {
            aA[0] = h2ex2(cvt_h2(sA0[1], sA0[0]));
            aA[1] = h2ex2(cvt_h2(sA0[3], sA0[2]));
            aA[2] = h2ex2(cvt_h2(sA1[1], sA1[0]));
            aA[3] = h2ex2(cvt_h2(sA1[3], sA1[2]));
            aB[0] = h2ex2(cvt_h2(sB0[1], sB0[0]));
            aB[1] = h2ex2(cvt_h2(sB0[3], sB0[2]));
            aB[2] = h2ex2(cvt_h2(sB1[1], sB1[0]));
            aB[3] = h2ex2(cvt_h2(sB1[3], sB1[2]));
        };
        auto do_PV = [&](int j) {
            mma16(liA, aA, ONES, ONES);
            mma16(liB, aB, ONES, ONES);
            #pragma unroll
            for (int p = 0; p < 4; p++) {
                uint32_t v[4];
                ldsm4t(v, K + lbase + (uint32_t)(j * 16 * KSTR + p * 16) * 2);
                mma16(o[2 * p],         aA, v[0], v[1]);
                mma16(o[2 * p + 1],     aA, v[2], v[3]);
                mma16(o[8 + 2 * p],     aB, v[0], v[1]);
                mma16(o[8 + 2 * p + 1], aB, v[2], v[3]);
            }
        };

        // pipelined: exp(j) hides under queued S(j+1) (+prior PV) tensor work
        do_S(0); do_exp();
        do_S(1); do_PV(0); do_exp();
        do_S(2); do_PV(1); do_exp();
        do_S(3); do_PV(2); do_exp();
        do_PV(3);
    }

    const float invA0 = 1.0f / liA[0];
    const float invA1 = 1.0f / liA[2];
    const float invB0 = 1.0f / liB[0];
    const float invB1 = 1.0f / liB[2];

    const int b_ = bh >> 3;
    const int h  = bh & 7;
    const size_t rbase = (size_t)b_ * NSEQ + q0 + w * 32 + g;
    #pragma unroll
    for (int nb = 0; nb < 8; nb++) {
        const int col = h * HDIM + nb * 8 + 2 * tg;
        *(float2*)&out[(rbase)      * DMODEL + col] =
            make_float2(o[nb][0] * invA0, o[nb][1] * invA0);
        *(float2*)&out[(rbase + 8)  * DMODEL + col] =
            make_float2(o[nb][2] * invA1, o[nb][3] * invA1);
        *(float2*)&out[(rbase + 16) * DMODEL + col] =
            make_float2(o[8 + nb][0] * invB0, o[8 + nb][1] * invB0);
        *(float2*)&out[(rbase + 24) * DMODEL + col] =
            make_float2(o[8 + nb][2] * invB1, o[8 + nb][3] * invB1);
    }
}

extern "C" void kernel_launch(void* const* d_in, const int* in_sizes, int n_in,
                              void* d_out, int out_size)
{
    const float* x  = (const float*)d_in[0];
    const float* Wq = (const float*)d_in[1];
    const float* bq = (const float*)d_in[2];
    const float* Wk = (const float*)d_in[3];
    const float* bk = (const float*)d_in[4];
    float* out = (float*)d_out;

    const int psmem = 192 * WSTR * 2;        // 27648 B
    const int asmem = 2 * 64 * KSTR * 2;     // 18432 B
    cudaFuncSetAttribute(proj_mma, cudaFuncAttributeMaxDynamicSharedMemorySize, psmem);
    cudaFuncSetAttribute(attn_mma, cudaFuncAttributeMaxDynamicSharedMemorySize, asmem);

    const float qscale = 0.044194173824159216f * 1.4426950408889634f; // D^-1/2 * log2e

    proj_mma<<<dim3(NH, (BQ * NSEQ) / 128, 2), 256, psmem>>>(x, Wq, bq, Wk, bk, qscale);
    attn_mma<<<dim3(NSEQ / 128, BQ * NH), 128, asmem>>>(out);
}